// round 17
// baseline (speedup 1.0000x reference)
#include <cuda_runtime.h>
#include <cuda_fp16.h>
#include <math.h>
#include <stdint.h>

#define B 8
#define C1 256
#define C2 256
#define NR 12800
#define NC 10

#define PSTR (8*256*88*44)   // parity-plane stride (elements)
#define HTOT (2*PSTR+8)      // one shift-copy length
#define NSPLIT 4
#define XN 221184            // 8*3*96*96

// ---- device scratch (no allocations allowed) ----
__device__ __half g_h4[4][HTOT];           // conv1 out: shift family, g_h4[s][j]=h[j+s]
__device__ __half g_xh[XN+8];              // x in fp16
__device__ __half g_xhs[XN+8];             // shifted: g_xhs[j] = g_xh[j+1]
__device__ __half g_wc1[256*256];          // conv1 weights fp16, K padded 243->256
__device__ __half g_wt[256*20736];         // prim weights, fp16
__device__ float g_acc[NSPLIT*256*12800];  // split-K partial sums
__device__ float g_u[B*C2*1600];           // squashed u
__device__ float g_uhat[B*NR*NC];
__device__ float g_bij[NR*NC];
__device__ float g_v[B*NC];
__device__ float g_t1[B*512];
__device__ float g_t2[B*1024];

__device__ __forceinline__ void cpa16(uint32_t dst, const void* src){
    asm volatile("cp.async.cg.shared.global [%0], [%1], 16;\n" :: "r"(dst), "l"(src));
}
__device__ __forceinline__ void cpa8(uint32_t dst, const void* src){
    asm volatile("cp.async.ca.shared.global [%0], [%1], 8;\n" :: "r"(dst), "l"(src));
}
__device__ __forceinline__ void cpa4(uint32_t dst, const void* src){
    asm volatile("cp.async.ca.shared.global [%0], [%1], 4;\n" :: "r"(dst), "l"(src));
}
__device__ __forceinline__ uint32_t smem_u32(const void* p){
    uint32_t a;
    asm("{ .reg .u64 t; cvta.to.shared.u64 t, %1; cvt.u32.u64 %0, t; }" : "=r"(a) : "l"(p));
    return a;
}

// ============================================================
// prep kernels
// ============================================================
__global__ void wround_kernel(const float* __restrict__ w, int off){
    int i = (blockIdx.x*256 + threadIdx.x)*4 + off;
    float4 v = *(const float4*)(w + i);
    *(__half2*)(g_wt + i)     = __floats2half2_rn(v.x, v.y);
    *(__half2*)(g_wt + i + 2) = __floats2half2_rn(v.z, v.w);
}
__global__ void xround_kernel(const float* __restrict__ x){
    int i = (blockIdx.x*256 + threadIdx.x)*4;   // 216*1024 = XN
    float4 v = *(const float4*)(x + i);
    __half h[4];
    h[0]=__float2half_rn(v.x); h[1]=__float2half_rn(v.y);
    h[2]=__float2half_rn(v.z); h[3]=__float2half_rn(v.w);
    #pragma unroll
    for (int k=0;k<4;k++){
        g_xh[i+k] = h[k];
        if (i+k > 0) g_xhs[i+k-1] = h[k];
    }
}
__global__ void wc1round_kernel(const float* __restrict__ w){
    int idx = blockIdx.x*256 + threadIdx.x;     // 65536
    int co = idx >> 8, k = idx & 255;
    g_wc1[idx] = (k < 243) ? __float2half_rn(w[co*243 + k]) : __half(0.f);
}

// ============================================================
// shared GEMM geometry: BM=128 BN=128 BK=32, 8 warps (64x32 warp tiles)
// A smem [m][k] fp16 row stride 40 halfs; B smem [k][n] fp16 row stride 136 halfs
// ============================================================
#define SA_BYTES (128*40*2)     // 10240
#define SB_BYTES (32*136*2)     // 8704
#define STAGE_BYTES (SA_BYTES + SB_BYTES)

// ============================================================
// conv1 as implicit GEMM: C[256][61952], K=243 (padded 256)
// epilogue: bias+relu -> fp16 -> 4-shift family g_h4
// ============================================================
#define C1_KT 8

__global__ __launch_bounds__(256, 2)
void conv1_mma_kernel(const float* __restrict__ bias){
    extern __shared__ __align__(16) char sm[];
    uint32_t smb = smem_u32(sm);
    int tid   = threadIdx.x;
    int ntile = blockIdx.x;       // 0..483
    int mtile = blockIdx.y;       // 0..1
    int co0 = mtile*128;
    int n0  = ntile*128;

    int am = tid >> 1;
    int ah = (tid & 1) * 16;
    const __half* wA = g_wc1 + (co0 + am)*256 + ah;
    uint32_t dA = smb + (uint32_t)(am*40 + ah)*2u;

    int kk = tid >> 3;
    int l7 = tid & 7;
    int q2 = (l7 & 3) * 2;
    int myOff[8];
    #pragma unroll
    for (int i=0;i<8;i++){
        int j = (l7 >> 2) + 2*i;
        int n = n0 + 8*j;
        int bb = n / 7744, p = n % 7744;
        int y = p / 88, xo = p % 88;
        myOff[i] = (bb*288 + y)*96 + xo + q2;    // 288 = 3*96 ; even base
    }
    uint32_t dB = smb + (uint32_t)(SA_BYTES + kk*272 + (l7>>2)*16 + (l7&3)*4);

    float acc[16][4];
    #pragma unroll
    for (int t=0;t<16;t++){
        #pragma unroll
        for (int qq=0;qq<4;qq++) acc[t][qq] = 0.f;
    }

    int warp = tid >> 5, lane = tid & 31;
    int wm = warp & 1;
    int wn = warp >> 1;
    int grp = lane >> 2, tig = lane & 3;

    uint32_t aRowByte = (uint32_t)(( (wm*64 + ((lane>>3)&1)*8 + (lane&7))*40
                                    + (lane>>4)*8 )*2);
    uint32_t bRowByte = (uint32_t)(( (lane&7) + ((lane>>3)&1)*8 )*272 + (wn*32)*2);

    auto issue = [&](int kt){
        uint32_t so = (uint32_t)((kt & 1) * STAGE_BYTES);
        const __half* a = wA + kt*32;
        cpa16(dA + so,      a);
        cpa16(dA + so + 16, a + 8);
        int k = kt*32 + kk;
        if (k >= 243) k = 0;                      // padded rows: weights are zero
        int ci = k / 81;
        int r  = k - ci*81;
        int ky = r / 9;
        int kx = r - ky*9;
        int add = ci*9216 + ky*96 + kx;           // 9216 = 96*96
        const __half* srcb = (kx & 1) ? (g_xhs + add - 1) : (g_xh + add);
        uint32_t sb = dB + so;
        #pragma unroll
        for (int i=0;i<8;i++)
            cpa4(sb + (uint32_t)(i*32), srcb + myOff[i]);
    };

    issue(0);
    asm volatile("cp.async.commit_group;\n");

    for (int kt=0; kt<C1_KT; kt++){
        if (kt+1 < C1_KT){
            issue(kt+1);
            asm volatile("cp.async.commit_group;\n");
            asm volatile("cp.async.wait_group 1;\n");
        } else {
            asm volatile("cp.async.wait_group 0;\n");
        }
        __syncthreads();

        uint32_t so  = (uint32_t)((kt & 1) * STAGE_BYTES);
        uint32_t sAb = smb + so + aRowByte;
        uint32_t sBb = smb + so + SA_BYTES + bRowByte;

        #pragma unroll
        for (int k16=0; k16<2; k16++){
            uint32_t afr[4][4], bfr[4][2];
            #pragma unroll
            for (int ms=0;ms<4;ms++){
                uint32_t ad = sAb + (uint32_t)(ms*1280 + k16*32);
                asm volatile(
                    "ldmatrix.sync.aligned.m8n8.x4.shared.b16 {%0,%1,%2,%3}, [%4];"
                    : "=r"(afr[ms][0]), "=r"(afr[ms][1]),
                      "=r"(afr[ms][2]), "=r"(afr[ms][3])
                    : "r"(ad));
            }
            #pragma unroll
            for (int ns=0;ns<4;ns++){
                uint32_t bd = sBb + (uint32_t)(ns*16 + k16*4352);
                asm volatile(
                    "ldmatrix.sync.aligned.m8n8.x2.trans.shared.b16 {%0,%1}, [%2];"
                    : "=r"(bfr[ns][0]), "=r"(bfr[ns][1])
                    : "r"(bd));
            }
            #pragma unroll
            for (int ms=0;ms<4;ms++){
                #pragma unroll
                for (int ns=0;ns<4;ns++){
                    float* c = acc[ms*4+ns];
                    asm volatile(
                        "mma.sync.aligned.m16n8k16.row.col.f32.f16.f16.f32 "
                        "{%0,%1,%2,%3}, {%4,%5,%6,%7}, {%8,%9}, {%0,%1,%2,%3};\n"
                        : "+f"(c[0]), "+f"(c[1]), "+f"(c[2]), "+f"(c[3])
                        : "r"(afr[ms][0]), "r"(afr[ms][1]),
                          "r"(afr[ms][2]), "r"(afr[ms][3]),
                          "r"(bfr[ns][0]), "r"(bfr[ns][1]));
                }
            }
        }
        __syncthreads();
    }

    // epilogue: bias + relu -> fp16 -> 4-shift family
    #pragma unroll
    for (int ms=0;ms<4;ms++){
        int coA = co0 + wm*64 + ms*16 + grp;
        float bA = bias[coA], bC = bias[coA + 8];
        #pragma unroll
        for (int ns=0;ns<4;ns++){
            int nb = n0 + wn*32 + ns*8 + 2*tig;
            float* c = acc[ms*4+ns];
            #pragma unroll
            for (int e=0;e<4;e++){
                int n  = nb + (e & 1);
                int co = coA + (e >> 1)*8;
                float val = c[e] + ((e >> 1) ? bC : bA);
                __half hv = __float2half_rn(fmaxf(val, 0.f));
                int bb = n / 7744, p = n % 7744;
                int y = p / 88, xo = p % 88;
                int gi = (xo & 1)*PSTR + (xo >> 1) + ((bb*C1 + co)*88 + y)*44;
                g_h4[0][gi] = hv;
                if (gi >= 1) g_h4[1][gi-1] = hv;
                if (gi >= 2) g_h4[2][gi-2] = hv;
                if (gi >= 3) g_h4[3][gi-3] = hv;
            }
        }
    }
}

// ============================================================
// prim conv implicit GEMM, fp16 mma + ldmatrix, split-K=4
// 3-stage cp.async ring, ONE barrier per k-tile, B gather via aligned cpa8
// ============================================================
#define KT_STEPS 162

__global__ __launch_bounds__(256, 2)
void prim_mma_kernel(){
    extern __shared__ __align__(16) char sm[];
    uint32_t smb = smem_u32(sm);
    int tid   = threadIdx.x;
    int ntile = blockIdx.x;       // 0..99
    int mtile = blockIdx.y;       // 0..1
    int split = blockIdx.z;       // 0..3
    int co0 = mtile*128;
    int n0  = ntile*128;
    int koff = split*(KT_STEPS*32);

    int am = tid >> 1;
    int ah = (tid & 1) * 16;
    const __half* wA = g_wt + (long long)(co0 + am)*20736 + koff + ah;
    uint32_t dA = smb + (uint32_t)(am*40 + ah)*2u;

    // B gather: k-row kk = tid>>3; lane l7 handles quad (l7&1) of blocks j=(l7>>1)+4i
    int kk = tid >> 3;
    int l7 = tid & 7;
    int q4 = (l7 & 1) * 4;            // half offset of quad within 8-n block
    int myOff[4];
    #pragma unroll
    for (int i=0;i<4;i++){
        int j = (l7 >> 1) + 4*i;
        int n = n0 + 8*j;
        int bb = n / 1600, p = n % 1600;
        int y = p / 40, x0 = p % 40;
        myOff[i] = (bb*22528 + 2*y)*44 + x0 + q4;   // == 0 mod 4
    }
    uint32_t dB = smb + (uint32_t)(SA_BYTES + kk*272 + (l7>>1)*16 + (l7&1)*8);

    float acc[16][4];
    #pragma unroll
    for (int t=0;t<16;t++){
        #pragma unroll
        for (int qq=0;qq<4;qq++) acc[t][qq] = 0.f;
    }

    int warp = tid >> 5, lane = tid & 31;
    int wm = warp & 1;
    int wn = warp >> 1;
    int grp = lane >> 2, tig = lane & 3;

    uint32_t aRowByte = (uint32_t)(( (wm*64 + ((lane>>3)&1)*8 + (lane&7))*40
                                    + (lane>>4)*8 )*2);
    uint32_t bRowByte = (uint32_t)(( (lane&7) + ((lane>>3)&1)*8 )*272 + (wn*32)*2);

    auto issue = [&](int kt){
        uint32_t so = (uint32_t)((kt % 3) * STAGE_BYTES);
        const __half* a = wA + kt*32;
        cpa16(dA + so,      a);
        cpa16(dA + so + 16, a + 8);
        int kB = koff + kt*32 + kk;
        int ci = kB / 81;
        int r  = kB - ci*81;
        int ky = r / 9;
        int kx = r - ky*9;
        int rb = ci*3872 + ky*44 + (kx >> 1);          // 3872 = 88*44
        int s  = rb & 3;
        const __half* srcb = g_h4[s] + (kx & 1)*PSTR + (rb - s);
        uint32_t sb = dB + so;
        #pragma unroll
        for (int i=0;i<4;i++)
            cpa8(sb + (uint32_t)(i*64), srcb + myOff[i]);
    };

    issue(0); asm volatile("cp.async.commit_group;\n");
    issue(1); asm volatile("cp.async.commit_group;\n");

    for (int kt=0; kt<KT_STEPS; kt++){
        if (kt+1 < KT_STEPS) asm volatile("cp.async.wait_group 1;\n");
        else                 asm volatile("cp.async.wait_group 0;\n");
        __syncthreads();

        if (kt+2 < KT_STEPS){
            issue(kt+2);
            asm volatile("cp.async.commit_group;\n");
        }

        uint32_t so  = (uint32_t)((kt % 3) * STAGE_BYTES);
        uint32_t sAb = smb + so + aRowByte;
        uint32_t sBb = smb + so + SA_BYTES + bRowByte;

        #pragma unroll
        for (int k16=0; k16<2; k16++){
            uint32_t afr[4][4], bfr[4][2];
            #pragma unroll
            for (int ms=0;ms<4;ms++){
                uint32_t ad = sAb + (uint32_t)(ms*1280 + k16*32);
                asm volatile(
                    "ldmatrix.sync.aligned.m8n8.x4.shared.b16 {%0,%1,%2,%3}, [%4];"
                    : "=r"(afr[ms][0]), "=r"(afr[ms][1]),
                      "=r"(afr[ms][2]), "=r"(afr[ms][3])
                    : "r"(ad));
            }
            #pragma unroll
            for (int ns=0;ns<4;ns++){
                uint32_t bd = sBb + (uint32_t)(ns*16 + k16*4352);
                asm volatile(
                    "ldmatrix.sync.aligned.m8n8.x2.trans.shared.b16 {%0,%1}, [%2];"
                    : "=r"(bfr[ns][0]), "=r"(bfr[ns][1])
                    : "r"(bd));
            }
            #pragma unroll
            for (int ms=0;ms<4;ms++){
                #pragma unroll
                for (int ns=0;ns<4;ns++){
                    float* c = acc[ms*4+ns];
                    asm volatile(
                        "mma.sync.aligned.m16n8k16.row.col.f32.f16.f16.f32 "
                        "{%0,%1,%2,%3}, {%4,%5,%6,%7}, {%8,%9}, {%0,%1,%2,%3};\n"
                        : "+f"(c[0]), "+f"(c[1]), "+f"(c[2]), "+f"(c[3])
                        : "r"(afr[ms][0]), "r"(afr[ms][1]),
                          "r"(afr[ms][2]), "r"(afr[ms][3]),
                          "r"(bfr[ns][0]), "r"(bfr[ns][1]));
                }
            }
        }
    }

    float* dst = g_acc + (size_t)split * (256*12800);
    #pragma unroll
    for (int ms=0;ms<4;ms++){
        int coA = co0 + wm*64 + ms*16 + grp;
        #pragma unroll
        for (int ns=0;ns<4;ns++){
            int nb = n0 + wn*32 + ns*8 + 2*tig;
            float* c = acc[ms*4+ns];
            #pragma unroll
            for (int e=0;e<4;e++){
                int n  = nb + (e & 1);
                int co = coA + (e >> 1)*8;
                dst[(size_t)co*12800 + n] = c[e];
            }
        }
    }
}

// ============================================================
// combine split-K partials + bias, then squash -> g_u
// ============================================================
__global__ void combine_squash_kernel(const float* __restrict__ bias){
    int vec  = blockIdx.x*8 + (threadIdx.x >> 5);   // 102400
    int lane = threadIdx.x & 31;
    int b  = vec / 12800;
    int rem = vec % 12800;
    int co = rem / 50;
    int j  = rem % 50;
    int n  = b*1600 + j*32 + lane;
    size_t ai = (size_t)co*12800 + n;
    float val = bias[co];
    #pragma unroll
    for (int s=0;s<NSPLIT;s++) val += g_acc[ai + (size_t)s*(256*12800)];
    float sq = val*val;
    #pragma unroll
    for (int off=16; off; off>>=1) sq += __shfl_xor_sync(0xffffffffu, sq, off);
    float scale = sq / ((1.f + sq) * sqrtf(sq));
    g_u[((size_t)(b*256 + co))*1600 + j*32 + lane] = val*scale;
}

// ============================================================
// u_hat / routing / decoder
// ============================================================
__global__ void uhat_kernel(const float* __restrict__ W){
    int idx = blockIdx.x*256 + threadIdx.x;
    if (idx >= NR*NC) return;
    int r = idx / 10;
    float wv[32];
    const float4* wp = (const float4*)(W + (long long)idx*32);
    #pragma unroll
    for (int q=0;q<8;q++){
        float4 t = wp[q];
        wv[q*4]=t.x; wv[q*4+1]=t.y; wv[q*4+2]=t.z; wv[q*4+3]=t.w;
    }
    #pragma unroll
    for (int b=0;b<8;b++){
        const float4* up = (const float4*)(g_u + ((long long)b*NR + r)*32);
        float s = 0.f;
        #pragma unroll
        for (int q=0;q<8;q++){
            float4 t = up[q];
            s += wv[q*4]*t.x + wv[q*4+1]*t.y + wv[q*4+2]*t.z + wv[q*4+3]*t.w;
        }
        g_uhat[b*NR*NC + idx] = s;
    }
}

__global__ void zero_bij(){
    int i = blockIdx.x*256 + threadIdx.x;
    if (i < NR*NC) g_bij[i] = 0.f;
}

__global__ void route_s_kernel(float* __restrict__ dout, int final_it){
    int c = blockIdx.x;
    int t = threadIdx.x;
    __shared__ float sred[9][256];

    float m = -1e30f;
    for (int r=t; r<NR; r+=256) m = fmaxf(m, g_bij[r*10 + c]);
    sred[0][t] = m; __syncthreads();
    for (int off=128; off; off>>=1){
        if (t < off) sred[0][t] = fmaxf(sred[0][t], sred[0][t+off]);
        __syncthreads();
    }
    m = sred[0][0];
    __syncthreads();

    float Z = 0.f, s[8] = {0,0,0,0,0,0,0,0};
    for (int r=t; r<NR; r+=256){
        float e = expf(g_bij[r*10 + c] - m);
        Z += e;
        const float* up = g_uhat + r*10 + c;
        #pragma unroll
        for (int b=0;b<8;b++) s[b] += e * up[b*128000];
    }
    sred[0][t] = Z;
    #pragma unroll
    for (int b=0;b<8;b++) sred[1+b][t] = s[b];
    __syncthreads();
    for (int off=128; off; off>>=1){
        if (t < off){
            #pragma unroll
            for (int q=0;q<9;q++) sred[q][t] += sred[q][t+off];
        }
        __syncthreads();
    }
    if (t < 8){
        float sv = sred[1+t][0] / sred[0][0];
        float sn = sv*sv;
        float v = sn*sv / ((1.f + sn) * sqrtf(sn));
        g_v[t*10 + c] = v;
        if (final_it) dout[t*10 + c] = v;
    }
}

__global__ void route_update_kernel(){
    int idx = blockIdx.x*256 + threadIdx.x;
    if (idx >= NR*NC) return;
    int c = idx % 10;
    float a = 0.f;
    #pragma unroll
    for (int b=0;b<8;b++) a += g_uhat[b*128000 + idx] * g_v[b*10 + c];
    g_bij[idx] += a;
}

__global__ void dec1_kernel(const float* __restrict__ w1, const float* __restrict__ b1){
    int idx = blockIdx.x*256 + threadIdx.x;
    int b = idx >> 9, j = idx & 511;
    float acc = b1[j];
    #pragma unroll
    for (int i=0;i<10;i++) acc += g_v[b*10 + i] * w1[i*512 + j];
    g_t1[idx] = fmaxf(acc, 0.f);
}

__global__ void dec2_kernel(const float* __restrict__ w2, const float* __restrict__ b2){
    __shared__ float sR[512];
    int j = blockIdx.x*256 + threadIdx.x;
    int b = blockIdx.y;
    for (int i=threadIdx.x; i<512; i+=256) sR[i] = g_t1[b*512 + i];
    __syncthreads();
    float acc = b2[j];
    for (int k=0;k<512;k++) acc += sR[k] * w2[k*1024 + j];
    g_t2[b*1024 + j] = fmaxf(acc, 0.f);
}

__global__ void dec3_kernel(const float* __restrict__ w3, const float* __restrict__ b3,
                            float* __restrict__ out){
    __shared__ float sRt[1024*8];
    int tid = threadIdx.x;
    int n = blockIdx.x*256 + tid;
    for (int i=tid; i<8192; i+=256){ int k = i>>3, b = i&7; sRt[i] = g_t2[b*1024 + k]; }
    __syncthreads();
    float acc[8];
    #pragma unroll
    for (int b=0;b<8;b++) acc[b] = 0.f;
    for (int k=0;k<1024;k++){
        float wv = w3[(long long)k*27648 + n];
        const float4* rp = (const float4*)(sRt + k*8);
        float4 a0 = rp[0], a1 = rp[1];
        acc[0] += wv*a0.x; acc[1] += wv*a0.y; acc[2] += wv*a0.z; acc[3] += wv*a0.w;
        acc[4] += wv*a1.x; acc[5] += wv*a1.y; acc[6] += wv*a1.z; acc[7] += wv*a1.w;
    }
    float bv = b3[n];
    #pragma unroll
    for (int b=0;b<8;b++){
        float z = acc[b] + bv;
        out[80 + b*27648 + n] = 1.f / (1.f + expf(-z));
    }
}

// ============================================================
extern "C" void kernel_launch(void* const* d_in, const int* in_sizes, int n_in,
                              void* d_out, int out_size){
    (void)in_sizes; (void)n_in; (void)out_size;
    const float* x   = (const float*)d_in[0];
    const float* c1w = (const float*)d_in[1];
    const float* c1b = (const float*)d_in[2];
    const float* pw  = (const float*)d_in[3];
    const float* pb  = (const float*)d_in[4];
    const float* dW  = (const float*)d_in[5];
    const float* w1  = (const float*)d_in[6];
    const float* b1  = (const float*)d_in[7];
    const float* w2  = (const float*)d_in[8];
    const float* b2  = (const float*)d_in[9];
    const float* w3  = (const float*)d_in[10];
    const float* b3  = (const float*)d_in[11];
    float* out = (float*)d_out;

    static int smem_set = 0;
    if (!smem_set){
        cudaFuncSetAttribute(prim_mma_kernel,
                             cudaFuncAttributeMaxDynamicSharedMemorySize, 3*STAGE_BYTES);
        cudaFuncSetAttribute(conv1_mma_kernel,
                             cudaFuncAttributeMaxDynamicSharedMemorySize, 2*STAGE_BYTES);
        smem_set = 1;
    }

    wround_kernel<<<2592, 256>>>(pw, 0);
    wround_kernel<<<2592, 256>>>(pw, 2592*1024);
    xround_kernel<<<216, 256>>>(x);
    wc1round_kernel<<<256, 256>>>(c1w);
    zero_bij<<<500, 256>>>();
    conv1_mma_kernel<<<dim3(484,2), 256, 2*STAGE_BYTES>>>(c1b);
    prim_mma_kernel<<<dim3(100,2,NSPLIT), 256, 3*STAGE_BYTES>>>();
    combine_squash_kernel<<<12800, 256>>>(pb);
    uhat_kernel<<<500, 256>>>(dW);
    for (int it=0; it<3; it++){
        route_s_kernel<<<10, 256>>>(out, it==2 ? 1 : 0);
        if (it < 2) route_update_kernel<<<500, 256>>>();
    }
    dec1_kernel<<<16, 256>>>(w1, b1);
    dec2_kernel<<<dim3(4,8), 256>>>(w2, b2);
    dec3_kernel<<<108, 256>>>(w3, b3, out);
}